// round 8
// baseline (speedup 1.0000x reference)
#include <cuda_runtime.h>
#include <math.h>

// EyesMouthLoss: mean(|pred-target| * (1 + priority*299))
// priority = clip(eye + mouth, 0, 1); region = max_j clip(1 - dist_j/15, 0, 1)
//
// Algebra:  max_j clip(1 - d_j/R) == clip(1 - sqrt(min_j d_j^2)/R)   (2 sqrts/px)
// Pruning:  landmark only touches rows with (y-cy)^2 < R^2 (~2 active/row avg)
// R8: warp-autonomous landmark prescan — lane l owns landmark 36+l (one LDG.64),
//     ballot -> active masks, ffs+shfl iteration over ~2 active landmarks.
//     No shared-mem prescan, no shared atomics, no prescan barriers.
//     Block = 256 thr = 8 warps = 2 rows (warp = quarter row, 4 px/lane).
// Tail: block reduce (1 barrier) + pre-scaled fire-and-forget f32 REDG;
//       out zeroed by async memset graph node.

#define H 512
#define W 512
#define C 3
#define B 16
#define NBLK (B * H / 2)           // 4096 blocks, 2 rows each
#define RADIUS2 225.0f
#define INV_R (1.0f / 15.0f)
#define INV_N (1.0f / (16.0f * 3.0f * 512.0f * 512.0f))
#define FULL 0xFFFFFFFFu

__global__ void __launch_bounds__(256) eml_main(
    const float* __restrict__ pred,
    const float* __restrict__ target,
    const int*   __restrict__ lm,
    float* __restrict__ out)
{
    const int tid  = threadIdx.x;
    const int wid  = tid >> 5;             // 0..7
    const int lane = tid & 31;
    const int rowg = blockIdx.x * 2 + (wid >> 2);   // global row = b*H + y
    const int b    = rowg >> 9;
    const int y    = rowg & (H - 1);
    const int q    = wid & 3;              // quarter of the row
    const int x0   = (q << 7) + (lane << 2);

    // ---- warp-level landmark prescan: lane owns landmark 36+lane ----
    const int  li  = 36 + lane;
    const int2 lxy = ((const int2*)lm)[b * 68 + li];   // one LDG.64
    const float cx = fminf(fmaxf((float)lxy.x, 0.0f), (float)(W - 1));
    const float cy = fminf(fmaxf((float)lxy.y, 0.0f), (float)(H - 1));
    const float dy  = (float)y - cy;
    const float dy2 = dy * dy;
    const bool  act = (dy2 < RADIUS2);
    const unsigned amask = __ballot_sync(FULL, act);
    const unsigned emask = amask & 0x00000FFFu;        // lanes 0..11  -> lm 36..47
    const unsigned mmask = amask & 0xFFFFF000u;        // lanes 12..31 -> lm 48..67

    // ---- weights for this lane's 4 pixels ----
    float wgt[4];
#pragma unroll
    for (int k = 0; k < 4; k++) wgt[k] = 1.0f;

    if (amask) {
        float emn[4], mmn[4];
#pragma unroll
        for (int k = 0; k < 4; k++) { emn[k] = 3.0e8f; mmn[k] = 3.0e8f; }

        unsigned m = emask;
        while (m) {
            const int j = __ffs(m) - 1; m &= m - 1;
            const float cxj = __shfl_sync(FULL, cx,  j);
            const float d2j = __shfl_sync(FULL, dy2, j);
#pragma unroll
            for (int k = 0; k < 4; k++) {
                const float dx = (float)(x0 + k) - cxj;
                emn[k] = fminf(emn[k], fmaf(dx, dx, d2j));
            }
        }
        m = mmask;
        while (m) {
            const int j = __ffs(m) - 1; m &= m - 1;
            const float cxj = __shfl_sync(FULL, cx,  j);
            const float d2j = __shfl_sync(FULL, dy2, j);
#pragma unroll
            for (int k = 0; k < 4; k++) {
                const float dx = (float)(x0 + k) - cxj;
                mmn[k] = fminf(mmn[k], fmaf(dx, dx, d2j));
            }
        }
#pragma unroll
        for (int k = 0; k < 4; k++) {
            const float e = (emn[k] < RADIUS2) ? (1.0f - sqrtf(emn[k]) * INV_R) : 0.0f;
            const float mm = (mmn[k] < RADIUS2) ? (1.0f - sqrtf(mmn[k]) * INV_R) : 0.0f;
            const float p = fminf(e + mm, 1.0f);
            wgt[k] = fmaf(p, 299.0f, 1.0f);
        }
    }

    // ---- tight load+consume loop ----
    const size_t rowbase = (size_t)b * (C * H * W) + (size_t)y * W + x0;
    float acc = 0.0f;
#pragma unroll
    for (int c = 0; c < C; c++) {
        const size_t off = rowbase + (size_t)c * (H * W);
        const float4 pv = *reinterpret_cast<const float4*>(pred + off);
        const float4 tv = *reinterpret_cast<const float4*>(target + off);
        acc = fmaf(fabsf(pv.x - tv.x), wgt[0], acc);
        acc = fmaf(fabsf(pv.y - tv.y), wgt[1], acc);
        acc = fmaf(fabsf(pv.z - tv.z), wgt[2], acc);
        acc = fmaf(fabsf(pv.w - tv.w), wgt[3], acc);
    }

    // ---- block reduce (single barrier) ----
#pragma unroll
    for (int s = 16; s > 0; s >>= 1)
        acc += __shfl_xor_sync(FULL, acc, s);

    __shared__ float s_part[8];
    if (lane == 0) s_part[wid] = acc;
    __syncthreads();

    if (tid == 0) {
        float bs = 0.0f;
#pragma unroll
        for (int wsl = 0; wsl < 8; wsl++) bs += s_part[wsl];
        atomicAdd(out, bs * INV_N);   // fire-and-forget REDG
    }
}

extern "C" void kernel_launch(void* const* d_in, const int* in_sizes, int n_in,
                              void* d_out, int out_size)
{
    const float* pred   = (const float*)d_in[0];
    const float* target = (const float*)d_in[1];
    const int*   lmk    = (const int*)d_in[2];
    float* out = (float*)d_out;

    cudaMemsetAsync(out, 0, sizeof(float), 0);   // memset node, graph-capturable
    eml_main<<<NBLK, 256>>>(pred, target, lmk, out);
}

// round 9
// speedup vs baseline: 1.2739x; 1.2739x over previous
#include <cuda_runtime.h>
#include <math.h>

// EyesMouthLoss: mean(|pred-target| * (1 + priority*299))
// priority = clip(eye + mouth, 0, 1); region = max_j clip(1 - dist_j/15, 0, 1)
//
// Algebra:  max_j clip(1 - d_j/R) == clip(1 - sqrt(min_j d_j^2)/R)  (2 sqrts/px)
// Pruning:  landmark only touches rows with (y-cy)^2 < R^2 (~2 active/row avg)
// R9: asymmetric load hoist — 3 pred float4 loads issued BEFORE the
//     prescan/weight phase (keeps DRAM pipe fed while computing weights),
//     target loads in the consume loop. launch_bounds(128,11) caps regs ~46
//     so occupancy stays ~69% (R6 failed this by holding all 6 -> 56 regs).
//     Warp-autonomous prescan (ballot + ffs/shfl), zero prescan barriers.
// Tail: block reduce + pre-scaled fire-and-forget f32 REDG; out zeroed by
//     async memset graph node.

#define H 512
#define W 512
#define C 3
#define B 16
#define NBLK (B * H)               // 8192 blocks, 1 row each
#define RADIUS2 225.0f
#define INV_R (1.0f / 15.0f)
#define INV_N (1.0f / (16.0f * 3.0f * 512.0f * 512.0f))
#define FULL 0xFFFFFFFFu

__global__ void __launch_bounds__(128, 11) eml_main(
    const float* __restrict__ pred,
    const float* __restrict__ target,
    const int*   __restrict__ lm,
    float* __restrict__ out)
{
    const int tid  = threadIdx.x;
    const int wid  = tid >> 5;             // 0..3 (quarter of row)
    const int lane = tid & 31;
    const int row  = blockIdx.x;           // b*H + y
    const int b    = row >> 9;
    const int y    = row & (H - 1);
    const int x0   = (wid << 7) + (lane << 2);

    // ---- hoist the 3 pred loads: in flight during the whole weight phase ----
    const size_t rowbase = (size_t)b * (C * H * W) + (size_t)y * W + x0;
    const float4 pv0 = *reinterpret_cast<const float4*>(pred + rowbase);
    const float4 pv1 = *reinterpret_cast<const float4*>(pred + rowbase + (size_t)(H * W));
    const float4 pv2 = *reinterpret_cast<const float4*>(pred + rowbase + (size_t)(2 * H * W));

    // ---- warp-level landmark prescan: lane owns landmark 36+lane ----
    const int2 lxy = ((const int2*)lm)[b * 68 + 36 + lane];   // one LDG.64
    const float cx = fminf(fmaxf((float)lxy.x, 0.0f), (float)(W - 1));
    const float cy = fminf(fmaxf((float)lxy.y, 0.0f), (float)(H - 1));
    const float dy  = (float)y - cy;
    const float dy2 = dy * dy;
    const unsigned amask = __ballot_sync(FULL, dy2 < RADIUS2);
    const unsigned emask = amask & 0x00000FFFu;        // lanes 0..11  -> lm 36..47
    const unsigned mmask = amask & 0xFFFFF000u;        // lanes 12..31 -> lm 48..67

    // ---- weights for this lane's 4 pixels ----
    float wgt[4];
#pragma unroll
    for (int k = 0; k < 4; k++) wgt[k] = 1.0f;

    if (amask) {
        float emn[4], mmn[4];
#pragma unroll
        for (int k = 0; k < 4; k++) { emn[k] = 3.0e8f; mmn[k] = 3.0e8f; }

        unsigned m = emask;
        while (m) {
            const int j = __ffs(m) - 1; m &= m - 1;
            const float cxj = __shfl_sync(FULL, cx,  j);
            const float d2j = __shfl_sync(FULL, dy2, j);
#pragma unroll
            for (int k = 0; k < 4; k++) {
                const float dx = (float)(x0 + k) - cxj;
                emn[k] = fminf(emn[k], fmaf(dx, dx, d2j));
            }
        }
        m = mmask;
        while (m) {
            const int j = __ffs(m) - 1; m &= m - 1;
            const float cxj = __shfl_sync(FULL, cx,  j);
            const float d2j = __shfl_sync(FULL, dy2, j);
#pragma unroll
            for (int k = 0; k < 4; k++) {
                const float dx = (float)(x0 + k) - cxj;
                mmn[k] = fminf(mmn[k], fmaf(dx, dx, d2j));
            }
        }
#pragma unroll
        for (int k = 0; k < 4; k++) {
            const float e  = (emn[k] < RADIUS2) ? (1.0f - sqrtf(emn[k]) * INV_R) : 0.0f;
            const float mm = (mmn[k] < RADIUS2) ? (1.0f - sqrtf(mmn[k]) * INV_R) : 0.0f;
            const float p  = fminf(e + mm, 1.0f);
            wgt[k] = fmaf(p, 299.0f, 1.0f);
        }
    }

    // ---- consume: target loads issue here, pred already resident ----
    const float4 tv0 = *reinterpret_cast<const float4*>(target + rowbase);
    const float4 tv1 = *reinterpret_cast<const float4*>(target + rowbase + (size_t)(H * W));
    const float4 tv2 = *reinterpret_cast<const float4*>(target + rowbase + (size_t)(2 * H * W));

    float acc = 0.0f;
    acc = fmaf(fabsf(pv0.x - tv0.x), wgt[0], acc);
    acc = fmaf(fabsf(pv0.y - tv0.y), wgt[1], acc);
    acc = fmaf(fabsf(pv0.z - tv0.z), wgt[2], acc);
    acc = fmaf(fabsf(pv0.w - tv0.w), wgt[3], acc);
    acc = fmaf(fabsf(pv1.x - tv1.x), wgt[0], acc);
    acc = fmaf(fabsf(pv1.y - tv1.y), wgt[1], acc);
    acc = fmaf(fabsf(pv1.z - tv1.z), wgt[2], acc);
    acc = fmaf(fabsf(pv1.w - tv1.w), wgt[3], acc);
    acc = fmaf(fabsf(pv2.x - tv2.x), wgt[0], acc);
    acc = fmaf(fabsf(pv2.y - tv2.y), wgt[1], acc);
    acc = fmaf(fabsf(pv2.z - tv2.z), wgt[2], acc);
    acc = fmaf(fabsf(pv2.w - tv2.w), wgt[3], acc);

    // ---- block reduce (single barrier) ----
#pragma unroll
    for (int s = 16; s > 0; s >>= 1)
        acc += __shfl_xor_sync(FULL, acc, s);

    __shared__ float s_part[4];
    if (lane == 0) s_part[wid] = acc;
    __syncthreads();

    if (tid == 0) {
        const float bs = s_part[0] + s_part[1] + s_part[2] + s_part[3];
        atomicAdd(out, bs * INV_N);   // fire-and-forget REDG
    }
}

extern "C" void kernel_launch(void* const* d_in, const int* in_sizes, int n_in,
                              void* d_out, int out_size)
{
    const float* pred   = (const float*)d_in[0];
    const float* target = (const float*)d_in[1];
    const int*   lmk    = (const int*)d_in[2];
    float* out = (float*)d_out;

    cudaMemsetAsync(out, 0, sizeof(float), 0);   // memset node, graph-capturable
    eml_main<<<NBLK, 128>>>(pred, target, lmk, out);
}